// round 17
// baseline (speedup 1.0000x reference)
#include <cuda_runtime.h>
#include <cuda_fp16.h>
#include <stdint.h>
#include <string.h>

#define THREADS 512
#define CTAS 296            // 2 per SM
#define ITEMS 4800          // 64 batch * 75 T-tiles (TTILE=4)

// Precomputed constant images (plain fp16, R6-proven layouts)
__device__ __align__(16) __half gPA[96*40];    // rows s*32+v, cols w, 80B stride
__device__ __align__(16) __half gW[192*72];    // rows k=(s*64+c), cols o, 144B stride
__device__ __align__(16) float gZb[1600];
__device__ __align__(16) float gScale[64], gShift[64];

// smem byte offsets
#define OFF_PA   0          // 96 x 80
#define OFF_W    7680       // 192 x 144
#define OFF_US0  35328      // U^T: 64 rows (c) x 272B (cols r'=t*32+w, t<4)
#define OFF_US1  52736
#define OFF_US2  70144
#define OFF_ZB   87552      // 1600 f32
#define OFF_BN   93952      // 64+64 f32
#define SMEM_TOTAL 94464

#define LDSM_X4T(r, a) \
    asm volatile("ldmatrix.sync.aligned.m8n8.x4.trans.shared.b16 {%0,%1,%2,%3}, [%4];" \
        : "=r"((r)[0]), "=r"((r)[1]), "=r"((r)[2]), "=r"((r)[3]) : "r"(a))
#define MMA(acc, a0, a1, a2, a3, b0, b1) \
    asm volatile("mma.sync.aligned.m16n8k16.row.col.f32.f16.f16.f32 " \
        "{%0,%1,%2,%3}, {%4,%5,%6,%7}, {%8,%9}, {%0,%1,%2,%3};" \
        : "+f"((acc)[0]), "+f"((acc)[1]), "+f"((acc)[2]), "+f"((acc)[3]) \
        : "r"(a0), "r"(a1), "r"(a2), "r"(a3), "r"(b0), "r"(b1))

__device__ __forceinline__ uint32_t cvta_smem(const void* p) {
    uint32_t a;
    asm("{ .reg .u64 t; cvta.to.shared.u64 t, %1; cvt.u32.u64 %0, t; }" : "=r"(a) : "l"(p));
    return a;
}
__device__ __forceinline__ uint32_t h2_bits(__half2 h) {
    uint32_t u; memcpy(&u, &h, 4); return u;
}
// R6-proven ldmatrix addressing (padded stride, no swizzle); base is SHARED-space addr
__device__ __forceinline__ uint32_t lm_addr(uint32_t base, int row0, int colByte,
                                            int stride, int lane) {
    return base + (uint32_t)((row0 + (lane & 15)) * stride + colByte + (lane >> 4) * 16);
}

// ---------------- setup ----------------
__global__ void setup_kernel(const float* __restrict__ PA, const float* __restrict__ Wc,
                             const float* __restrict__ bc, const float* __restrict__ gamma,
                             const float* __restrict__ beta, const float* __restrict__ mean,
                             const float* __restrict__ var)
{
    const int tid = threadIdx.x;
    __half z = __float2half(0.f);
    for (int i = tid; i < 96*40;  i += 512) gPA[i] = z;
    for (int i = tid; i < 192*72; i += 512) gW[i]  = z;
    __syncthreads();
    for (int i = tid; i < 1875; i += 512) {       // PA rows s*32+v, cols w
        int s = i / 625, r = i - s*625, v = r / 25, w = r - v*25;
        gPA[(s*32 + v)*40 + w] = __float2half_rn(PA[i]);
    }
    for (int i = tid; i < 192*64; i += 512) {     // W rows k=s*64+c, cols o
        int so = i >> 6, c = i & 63, s = so >> 6, o = so & 63;
        gW[(s*64 + c)*72 + o] = __float2half_rn(Wc[i]);
    }
    for (int i = tid; i < 1600; i += 512) {
        int o = i / 25, w = i - o*25;
        float acc = 0.f;
        for (int s = 0; s < 3; s++) {
            float cs = 0.f;
            for (int v = 0; v < 25; v++) cs += PA[s*625 + v*25 + w];
            acc += bc[s*64 + o] * cs;
        }
        gZb[i] = acc;
    }
    if (tid < 64) {
        float sc = gamma[tid] * rsqrtf(var[tid] + 1e-5f);
        gScale[tid] = sc; gShift[tid] = beta[tid] - mean[tid] * sc;
    }
}

// ---------------- main persistent kernel ----------------
__global__ __launch_bounds__(THREADS, 2)
void stgcn_main(const float* __restrict__ x, float* __restrict__ out)
{
    extern __shared__ char sm[];
    const uint32_t sb = cvta_smem(sm);
    const int tid = threadIdx.x, wid = tid >> 5, lane = tid & 31;

    // one-time: copy constants (every U byte read is rewritten every item)
    {
        for (int i = tid; i < 480; i += THREADS)
            ((uint4*)(sm + OFF_PA))[i] = ((const uint4*)gPA)[i];
        for (int i = tid; i < 1728; i += THREADS)
            ((uint4*)(sm + OFF_W))[i] = ((const uint4*)gW)[i];
        for (int i = tid; i < 400; i += THREADS)
            ((uint4*)(sm + OFF_ZB))[i] = ((const uint4*)gZb)[i];
        if (tid < 64) {
            ((float*)(sm + OFF_BN))[tid]      = gScale[tid];
            ((float*)(sm + OFF_BN))[64 + tid] = gShift[tid];
        }
    }

    const int mt  = wid;                        // stage-1: 16 warps x 16 M-rows
    const int mt2 = wid & 7, ng2 = wid >> 3;    // stage-2: 8 x 16 M-rows, 2 x 32 N-cols

    // A-frag per-thread invariants (proven lane map)
    const int arow = mt*16 + (lane >> 2);       // X row = c*4+t
    const int aca = arow >> 2, ata = arow & 3;
    const int av  = (lane & 3) * 2;

    // epilogue invariants
    const int erb = mt2*16 + (lane >> 2);
    const int eob = ng2*32 + 2*(lane & 3);

    // A-fragment builder: 16 LDG + 8 packs, direct to registers
    auto loadA = [&](int item, uint32_t Ah[2][4]) {
        const int b = item & 63, tile = item >> 6;
        const int n = b >> 1, m = b & 1, t0 = tile * 4;
        const long long ga = (long long)n*960000 + aca*15000 + (t0 + ata)*50 + m;
        const long long gb2 = ga + 30000;          // row+8 -> c+2
        #pragma unroll
        for (int k16 = 0; k16 < 2; k16++)
            #pragma unroll
            for (int kh = 0; kh < 2; kh++) {
                int v0 = k16*16 + kh*8 + av, v1 = v0 + 1;
                int o0 = (v0 < 25 ? v0 : 24)*2, o1 = (v1 < 25 ? v1 : 24)*2;
                float a0 = (v0 < 25) ? x[ga  + o0] : 0.f;
                float a1 = (v1 < 25) ? x[ga  + o1] : 0.f;
                float b0 = (v0 < 25) ? x[gb2 + o0] : 0.f;
                float b1 = (v1 < 25) ? x[gb2 + o1] : 0.f;
                Ah[k16][2*kh + 0] = h2_bits(__floats2half2_rn(a0, a1));
                Ah[k16][2*kh + 1] = h2_bits(__floats2half2_rn(b0, b1));
            }
    };

    // stage1: u_s = X * PA_s (M=256,K=32,N=32); scatter half2 into U^T[c][t*32+w]
    auto stage1 = [&](int s, int usOff, const uint32_t Ah[2][4]) {
        uint32_t Bh[2][2][4];
        #pragma unroll
        for (int k16 = 0; k16 < 2; k16++)
            #pragma unroll
            for (int nh = 0; nh < 2; nh++)
                LDSM_X4T(Bh[k16][nh],
                         lm_addr(sb + OFF_PA, s*32 + k16*16, nh*32, 80, lane));
        float acc[4][4];
        #pragma unroll
        for (int j = 0; j < 4; j++)
            #pragma unroll
            for (int e = 0; e < 4; e++) acc[j][e] = 0.f;
        #pragma unroll
        for (int k16 = 0; k16 < 2; k16++)
            #pragma unroll
            for (int j = 0; j < 4; j++)
                MMA(acc[j], Ah[k16][0], Ah[k16][1], Ah[k16][2], Ah[k16][3],
                    Bh[k16][j>>1][(j&1)*2], Bh[k16][j>>1][(j&1)*2+1]);
        #pragma unroll
        for (int half = 0; half < 2; half++) {
            int grow = mt*16 + (lane >> 2) + half*8;   // row = c*4+t
            int c = grow >> 2, t = grow & 3;
            int base = usOff + c*272 + (t*32 + 2*(lane & 3))*2;
            #pragma unroll
            for (int j = 0; j < 4; j++) {
                __half2 hv = __floats2half2_rn(acc[j][half*2], acc[j][half*2+1]);
                *(__half2*)(sm + base + j*16) = hv;
            }
        }
    };
    // stage2: zacc += U^T(trans-A) * W_s^T (M=128 r', K=64 c, N=64 o)
    auto stage2 = [&](int s, int usOff, float zacc[4][4]) {
        #pragma unroll
        for (int k16 = 0; k16 < 4; k16++) {
            uint32_t Au[4], Bw[2][4];
            LDSM_X4T(Au, lm_addr(sb + usOff, k16*16, mt2*32, 272, lane));
            #pragma unroll
            for (int nh = 0; nh < 2; nh++)
                LDSM_X4T(Bw[nh],
                         lm_addr(sb + OFF_W, s*64 + k16*16, ng2*64 + nh*32, 144, lane));
            #pragma unroll
            for (int j = 0; j < 4; j++)       // trans-A order: a0,a2,a1,a3
                MMA(zacc[j], Au[0], Au[2], Au[1], Au[3],
                    Bw[j>>1][(j&1)*2], Bw[j>>1][(j&1)*2+1]);
        }
    };

    uint32_t Ah[2][4];
    if (blockIdx.x < ITEMS) loadA(blockIdx.x, Ah);
    __syncthreads();                            // constants ready

    for (int item = blockIdx.x; item < ITEMS; item += CTAS) {
        const int b = item & 63, tile = item >> 6;
        const int n = b >> 1, m = b & 1, t0 = tile * 4;

        float zacc[4][4];
        #pragma unroll
        for (int j = 0; j < 4; j++)
            #pragma unroll
            for (int e = 0; e < 4; e++) zacc[j][e] = 0.f;

        // s1(0)->U0 : U0's prior readers (s2(0) of item-1) finished 2 barriers ago
        stage1(0, OFF_US0, Ah);
        __syncthreads();                        // barA: U0 ready
        stage1(1, OFF_US1, Ah);
        stage2(0, OFF_US0, zacc);
        __syncthreads();                        // barB: U1 ready, U0 reads done
        stage1(2, OFF_US2, Ah);
        stage2(1, OFF_US1, zacc);
        __syncthreads();                        // barC: U2 ready, U1 reads done

        // prefetch next item's A-fragments (Ah dead after stage1(2));
        // LDG latency hides under stage2(2) + epilogue
        {
            int nxt = item + CTAS;
            loadA(nxt < ITEMS ? nxt : item, Ah);
        }
        stage2(2, OFF_US2, zacc);

        // epilogue: BN + relu + residual(global, exact) + relu + store
        {
            const float* zbS = (const float*)(sm + OFF_ZB);
            const float* scS = (const float*)(sm + OFF_BN);
            const float* shS = scS + 64;
            const long long gb = (long long)n*960000 + t0*50 + m;
            #pragma unroll
            for (int half = 0; half < 2; half++) {
                int rp = erb + half*8;          // r' = t*32 + w
                int t = rp >> 5, w = rp & 31;
                if (w < 25) {
                    long long gtw = gb + t*50 + w*2;
                    #pragma unroll
                    for (int j = 0; j < 4; j++)
                        #pragma unroll
                        for (int e = 0; e < 2; e++) {
                            int o = eob + j*8 + e;
                            float z = zacc[j][half*2 + e] + zbS[o*25 + w];
                            float zn = fmaxf(fmaf(z, scS[o], shS[o]), 0.f);
                            long long gi = gtw + o*15000;
                            out[gi] = fmaxf(zn + x[gi], 0.f);
                        }
                }
            }
        }
        // no trailing barrier: next s1(0) writes U0, whose readers completed
        // before this item's barB (two barriers ago)
    }
}

extern "C" void kernel_launch(void* const* d_in, const int* in_sizes, int n_in,
                              void* d_out, int out_size)
{
    const float* x     = (const float*)d_in[0];
    const float* PA    = (const float*)d_in[1];
    const float* Wc    = (const float*)d_in[2];
    const float* bc    = (const float*)d_in[3];
    const float* gamma = (const float*)d_in[4];
    const float* beta  = (const float*)d_in[5];
    const float* mean  = (const float*)d_in[6];
    const float* var   = (const float*)d_in[7];

    setup_kernel<<<1, 512>>>(PA, Wc, bc, gamma, beta, mean, var);

    cudaFuncSetAttribute(stgcn_main, cudaFuncAttributeMaxDynamicSharedMemorySize, SMEM_TOTAL);
    stgcn_main<<<CTAS, THREADS, SMEM_TOTAL>>>(x, (float*)d_out);
}